// round 1
// baseline (speedup 1.0000x reference)
#include <cuda_runtime.h>

#define E_EDGES 2000000
#define N_NODES 50000
#define D 32

// ---------------- scratch (static device globals; no runtime alloc) ----------------
__device__ float g_s0[N_NODES * D];            // segment sums, layer 0
__device__ float g_s1[N_NODES * D];            // segment sums, layer 1
__device__ float g_h1[(size_t)E_EDGES * D];    // h after layer 0, TRANSPOSED [D][E]
__device__ float g_vals[E_EDGES];              // head logits
__device__ int   g_mi[N_NODES];                // per-node max (order-encoded int)
__device__ float g_dsum[N_NODES];              // softmax denominators

__device__ __forceinline__ float lrelu(float x) { return x > 0.f ? x : 0.01f * x; }

// order-preserving float<->int encoding for atomicMax
__device__ __forceinline__ int fenc(float f) {
    int i = __float_as_int(f);
    return i >= 0 ? i : (i ^ 0x7FFFFFFF);
}
__device__ __forceinline__ float fdec(int i) {
    return __int_as_float(i >= 0 ? i : (i ^ 0x7FFFFFFF));
}

// vectorized fire-and-forget reduction (sm_90+)
__device__ __forceinline__ void red_add4(float* p, float4 v) {
    asm volatile("red.global.add.v4.f32 [%0], {%1,%2,%3,%4};"
                 :: "l"(p), "f"(v.x), "f"(v.y), "f"(v.z), "f"(v.w) : "memory");
}

// y[32] = x[32] @ W(32x32, shared, row-major) + b ; optional leaky-relu
__device__ __forceinline__ void mat32(const float* x, const float* sW, const float* sB,
                                      float* y, bool act) {
#pragma unroll
    for (int d = 0; d < D; d += 4) {
        float4 acc = *(const float4*)&sB[d];
#pragma unroll
        for (int k = 0; k < D; ++k) {
            float4 w = *(const float4*)&sW[k * D + d];
            float xv = x[k];
            acc.x = fmaf(xv, w.x, acc.x);
            acc.y = fmaf(xv, w.y, acc.y);
            acc.z = fmaf(xv, w.z, acc.z);
            acc.w = fmaf(xv, w.w, acc.w);
        }
        if (act) { acc.x = lrelu(acc.x); acc.y = lrelu(acc.y); acc.z = lrelu(acc.z); acc.w = lrelu(acc.w); }
        y[d] = acc.x; y[d + 1] = acc.y; y[d + 2] = acc.z; y[d + 3] = acc.w;
    }
}

// ---------------- init: zero accumulators ----------------
__global__ void kinit() {
    int i = blockIdx.x * blockDim.x + threadIdx.x;
    if (i < N_NODES * D) { g_s0[i] = 0.f; g_s1[i] = 0.f; }
    if (i < N_NODES)     { g_mi[i] = (int)0x80000000; g_dsum[i] = 0.f; }
}

// ---------------- K0: t0 = TMLP0(h0(a)) folded; scatter into s0 ----------------
__global__ void k0(const float* __restrict__ ea, const int* __restrict__ idx,
                   const float* __restrict__ w_in, const float* __restrict__ b_in,
                   const float* __restrict__ tw1, const float* __restrict__ tb1,
                   const float* __restrict__ tw2, const float* __restrict__ tb2) {
    __shared__ float sP[D], sQ[D], sW2[D * D], sB2[D];
    int t = threadIdx.x;
    if (t < D) {
        float p = 0.f, q = 0.f;
        for (int k = 0; k < D; ++k) {
            p = fmaf(w_in[k], tw1[k * D + t], p);
            q = fmaf(b_in[k], tw1[k * D + t], q);
        }
        sP[t] = p; sQ[t] = q + tb1[t]; sB2[t] = tb2[t];
    }
    for (int i = t; i < D * D; i += blockDim.x) sW2[i] = tw2[i];
    __syncthreads();

    int e = blockIdx.x * blockDim.x + t;
    if (e >= E_EDGES) return;
    float a = ea[e];
    int node = idx[e];

    float z[D];
#pragma unroll
    for (int d = 0; d < D; ++d) z[d] = lrelu(fmaf(a, sP[d], sQ[d]));

    float* srow = g_s0 + (size_t)node * D;
#pragma unroll
    for (int d = 0; d < D; d += 4) {
        float4 acc = *(const float4*)&sB2[d];
#pragma unroll
        for (int k = 0; k < D; ++k) {
            float4 w = *(const float4*)&sW2[k * D + d];
            float xv = z[k];
            acc.x = fmaf(xv, w.x, acc.x);
            acc.y = fmaf(xv, w.y, acc.y);
            acc.z = fmaf(xv, w.z, acc.z);
            acc.w = fmaf(xv, w.w, acc.w);
        }
        red_add4(srow + d, acc);
    }
}

// ---------------- K1: h1 = UPD0(h0, s0[idx]); t1 = TMLP1(h1); scatter s1; store h1 ----
__global__ void k1(const float* __restrict__ ea, const int* __restrict__ idx,
                   const float* __restrict__ w_in, const float* __restrict__ b_in,
                   const float* __restrict__ tw1, const float* __restrict__ tb1,
                   const float* __restrict__ tw2, const float* __restrict__ tb2,
                   const float* __restrict__ uw1, const float* __restrict__ ub1,
                   const float* __restrict__ uw2, const float* __restrict__ ub2) {
    __shared__ float sP[D], sQ[D];                 // h0 folded through uw1[0][0:32]
    __shared__ float sU1b[D * D];                  // uw1[0][32:64]
    __shared__ float sU2[D * D], sUB2[D];          // uw2[0], ub2[0]
    __shared__ float sT1[D * D], sTB1[D];          // tw1[1], tb1[1]
    __shared__ float sT2[D * D], sTB2[D];          // tw2[1], tb2[1]
    int t = threadIdx.x;
    if (t < D) {
        float p = 0.f, q = 0.f;
        for (int k = 0; k < D; ++k) {
            p = fmaf(w_in[k], uw1[k * D + t], p);
            q = fmaf(b_in[k], uw1[k * D + t], q);
        }
        sP[t] = p; sQ[t] = q + ub1[t];
        sUB2[t] = ub2[t]; sTB1[t] = tb1[D + t]; sTB2[t] = tb2[D + t];
    }
    for (int i = t; i < D * D; i += blockDim.x) {
        sU1b[i] = uw1[D * D + i];      // rows 32..63 of uw1[0]
        sU2[i]  = uw2[i];
        sT1[i]  = tw1[D * D + i];      // tw1[1]
        sT2[i]  = tw2[D * D + i];      // tw2[1]
    }
    __syncthreads();

    int e = blockIdx.x * blockDim.x + t;
    if (e >= E_EDGES) return;
    float a = ea[e];
    int node = idx[e];

    float sg[D];
    {
        const float4* sg4 = (const float4*)(g_s0 + (size_t)node * D);
#pragma unroll
        for (int j = 0; j < D / 4; ++j) {
            float4 v = sg4[j];
            sg[4 * j] = v.x; sg[4 * j + 1] = v.y; sg[4 * j + 2] = v.z; sg[4 * j + 3] = v.w;
        }
    }

    // z = lrelu(a*P + Q + sg @ U1b)
    float z[D];
#pragma unroll
    for (int d = 0; d < D; d += 4) {
        float4 acc = make_float4(fmaf(a, sP[d], sQ[d]), fmaf(a, sP[d + 1], sQ[d + 1]),
                                 fmaf(a, sP[d + 2], sQ[d + 2]), fmaf(a, sP[d + 3], sQ[d + 3]));
#pragma unroll
        for (int k = 0; k < D; ++k) {
            float4 w = *(const float4*)&sU1b[k * D + d];
            float xv = sg[k];
            acc.x = fmaf(xv, w.x, acc.x);
            acc.y = fmaf(xv, w.y, acc.y);
            acc.z = fmaf(xv, w.z, acc.z);
            acc.w = fmaf(xv, w.w, acc.w);
        }
        z[d] = lrelu(acc.x); z[d + 1] = lrelu(acc.y); z[d + 2] = lrelu(acc.z); z[d + 3] = lrelu(acc.w);
    }

    float h1[D];
    mat32(z, sU2, sUB2, h1, false);

    // persist h1 transposed [D][E] (coalesced)
#pragma unroll
    for (int d = 0; d < D; ++d) g_h1[(size_t)d * E_EDGES + e] = h1[d];

    // t1 = lrelu(h1@T1 + TB1) @ T2 + TB2; scatter into s1
    float z2[D];
    mat32(h1, sT1, sTB1, z2, true);

    float* srow = g_s1 + (size_t)node * D;
#pragma unroll
    for (int d = 0; d < D; d += 4) {
        float4 acc = *(const float4*)&sTB2[d];
#pragma unroll
        for (int k = 0; k < D; ++k) {
            float4 w = *(const float4*)&sT2[k * D + d];
            float xv = z2[k];
            acc.x = fmaf(xv, w.x, acc.x);
            acc.y = fmaf(xv, w.y, acc.y);
            acc.z = fmaf(xv, w.z, acc.z);
            acc.w = fmaf(xv, w.w, acc.w);
        }
        red_add4(srow + d, acc);
    }
}

// ---------------- K2: h2 = UPD1(h1, s1[idx]); head -> logits; atomicMax per node ----
__global__ void k2(const float* __restrict__ ea, const int* __restrict__ idx,
                   const float* __restrict__ w_in, const float* __restrict__ b_in,
                   const float* __restrict__ uw1, const float* __restrict__ ub1,
                   const float* __restrict__ uw2, const float* __restrict__ ub2,
                   const float* __restrict__ hw1, const float* __restrict__ hb1,
                   const float* __restrict__ hw2, const float* __restrict__ hb2,
                   const float* __restrict__ hw3, const float* __restrict__ hb3) {
    __shared__ float sU1a[D * D], sU1b[D * D], sU2[D * D], sUB1[D], sUB2[D];
    __shared__ float sPH[D], sQH[D];               // h0 folded through hw1[0:32]
    __shared__ float sH1b[D * D], sH2[D * D], sHB2[D], sH3[D];
    __shared__ float sHB3;
    int t = threadIdx.x;
    const float* u1 = uw1 + 2 * D * D;             // uw1[1] (layer stride 64*32)
    if (t < D) {
        float p = 0.f, q = 0.f;
        for (int k = 0; k < D; ++k) {
            p = fmaf(w_in[k], hw1[k * D + t], p);
            q = fmaf(b_in[k], hw1[k * D + t], q);
        }
        sPH[t] = p; sQH[t] = q + hb1[t];
        sUB1[t] = ub1[D + t]; sUB2[t] = ub2[D + t]; sHB2[t] = hb2[t]; sH3[t] = hw3[t];
    }
    if (t == 0) sHB3 = hb3[0];
    for (int i = t; i < D * D; i += blockDim.x) {
        sU1a[i] = u1[i];
        sU1b[i] = u1[D * D + i];
        sU2[i]  = uw2[D * D + i];
        sH1b[i] = hw1[D * D + i];
        sH2[i]  = hw2[i];
    }
    __syncthreads();

    int e = blockIdx.x * blockDim.x + t;
    if (e >= E_EDGES) return;
    float a = ea[e];
    int node = idx[e];

    float h1[D];
#pragma unroll
    for (int d = 0; d < D; ++d) h1[d] = g_h1[(size_t)d * E_EDGES + e];

    float sg[D];
    {
        const float4* sg4 = (const float4*)(g_s1 + (size_t)node * D);
#pragma unroll
        for (int j = 0; j < D / 4; ++j) {
            float4 v = sg4[j];
            sg[4 * j] = v.x; sg[4 * j + 1] = v.y; sg[4 * j + 2] = v.z; sg[4 * j + 3] = v.w;
        }
    }

    // z = lrelu(h1@U1a + sg@U1b + UB1)
    float z[D];
#pragma unroll
    for (int d = 0; d < D; d += 4) {
        float4 acc = *(const float4*)&sUB1[d];
#pragma unroll
        for (int k = 0; k < D; ++k) {
            float4 wa = *(const float4*)&sU1a[k * D + d];
            float4 wb = *(const float4*)&sU1b[k * D + d];
            float xa = h1[k], xb = sg[k];
            acc.x = fmaf(xa, wa.x, acc.x); acc.x = fmaf(xb, wb.x, acc.x);
            acc.y = fmaf(xa, wa.y, acc.y); acc.y = fmaf(xb, wb.y, acc.y);
            acc.z = fmaf(xa, wa.z, acc.z); acc.z = fmaf(xb, wb.z, acc.z);
            acc.w = fmaf(xa, wa.w, acc.w); acc.w = fmaf(xb, wb.w, acc.w);
        }
        z[d] = lrelu(acc.x); z[d + 1] = lrelu(acc.y); z[d + 2] = lrelu(acc.z); z[d + 3] = lrelu(acc.w);
    }

    float h2[D];
    mat32(z, sU2, sUB2, h2, false);

    // v1 = lrelu(a*PH + QH + h2 @ H1b)
    float v1[D];
#pragma unroll
    for (int d = 0; d < D; d += 4) {
        float4 acc = make_float4(fmaf(a, sPH[d], sQH[d]), fmaf(a, sPH[d + 1], sQH[d + 1]),
                                 fmaf(a, sPH[d + 2], sQH[d + 2]), fmaf(a, sPH[d + 3], sQH[d + 3]));
#pragma unroll
        for (int k = 0; k < D; ++k) {
            float4 w = *(const float4*)&sH1b[k * D + d];
            float xv = h2[k];
            acc.x = fmaf(xv, w.x, acc.x);
            acc.y = fmaf(xv, w.y, acc.y);
            acc.z = fmaf(xv, w.z, acc.z);
            acc.w = fmaf(xv, w.w, acc.w);
        }
        v1[d] = lrelu(acc.x); v1[d + 1] = lrelu(acc.y); v1[d + 2] = lrelu(acc.z); v1[d + 3] = lrelu(acc.w);
    }

    float v2[D];
    mat32(v1, sH2, sHB2, v2, true);

    float val = sHB3;
#pragma unroll
    for (int k = 0; k < D; ++k) val = fmaf(v2[k], sH3[k], val);

    g_vals[e] = val;
    atomicMax(&g_mi[node], fenc(val));
}

// ---------------- K3: e = exp(v - m[idx]); accumulate denom; stage e in out --------
__global__ void k3(const int* __restrict__ idx, float* __restrict__ out) {
    int e = blockIdx.x * blockDim.x + threadIdx.x;
    if (e >= E_EDGES) return;
    int node = idx[e];
    float m = fdec(g_mi[node]);
    float ex = expf(g_vals[e] - m);
    atomicAdd(&g_dsum[node], ex);
    out[e] = ex;
}

// ---------------- K4: normalize --------------------------------------------------
__global__ void k4(const int* __restrict__ idx, float* __restrict__ out) {
    int e = blockIdx.x * blockDim.x + threadIdx.x;
    if (e >= E_EDGES) return;
    out[e] = out[e] / g_dsum[idx[e]];
}

// ---------------- launcher --------------------------------------------------------
extern "C" void kernel_launch(void* const* d_in, const int* in_sizes, int n_in,
                              void* d_out, int out_size) {
    const float* ea   = (const float*)d_in[0];
    const int*   eidx = (const int*)d_in[1];   // row 0 = source nodes
    const float* w_in = (const float*)d_in[2];
    const float* b_in = (const float*)d_in[3];
    const float* tw1  = (const float*)d_in[4];
    const float* tb1  = (const float*)d_in[5];
    const float* tw2  = (const float*)d_in[6];
    const float* tb2  = (const float*)d_in[7];
    const float* uw1  = (const float*)d_in[8];
    const float* ub1  = (const float*)d_in[9];
    const float* uw2  = (const float*)d_in[10];
    const float* ub2  = (const float*)d_in[11];
    const float* hw1  = (const float*)d_in[12];
    const float* hb1  = (const float*)d_in[13];
    const float* hw2  = (const float*)d_in[14];
    const float* hb2  = (const float*)d_in[15];
    const float* hw3  = (const float*)d_in[16];
    const float* hb3  = (const float*)d_in[17];
    float* out = (float*)d_out;

    const int TB = 256;
    kinit<<<(N_NODES * D + TB - 1) / TB, TB>>>();
    int gb = (E_EDGES + TB - 1) / TB;
    k0<<<gb, TB>>>(ea, eidx, w_in, b_in, tw1, tb1, tw2, tb2);
    k1<<<gb, TB>>>(ea, eidx, w_in, b_in, tw1, tb1, tw2, tb2, uw1, ub1, uw2, ub2);
    k2<<<gb, TB>>>(ea, eidx, w_in, b_in, uw1, ub1, uw2, ub2,
                   hw1, hb1, hw2, hb2, hw3, hb3);
    k3<<<gb, TB>>>(eidx, out);
    k4<<<gb, TB>>>(eidx, out);
}